// round 2
// baseline (speedup 1.0000x reference)
#include <cuda_runtime.h>
#include <math.h>

#define Bz 32
#define Lz 4096
#define Dz 1024
#define SPLITS 16
#define WARPS 8
#define ROWS_PER_WARP (Lz / SPLITS / WARPS)   // 32
#define NPART (SPLITS * WARPS)                // 128 partials per batch
#define TOTAL_PART (Bz * NPART)               // 4096

// Scratch for warp partials (no cudaMalloc allowed).
__device__ float g_m[TOTAL_PART];
__device__ float g_s[TOTAL_PART];
__device__ float g_acc[TOTAL_PART][Dz];       // 16 MB

// ---------------------------------------------------------------------------
// Pass 1: per-warp online-softmax over its slice of rows.
// Each lane owns 32 of the 1024 feature dims (8 x float4, strided by 128).
// Masked rows are skipped BEFORE loading the 4KB row -> ~50% traffic saved.
// ---------------------------------------------------------------------------
__global__ void __launch_bounds__(256, 2)
tap_pass1(const float* __restrict__ seq,
          const int* __restrict__ mask,       // bool marshalled as int32
          const float* __restrict__ query)
{
    const int b     = blockIdx.x / SPLITS;
    const int split = blockIdx.x % SPLITS;
    const int warp  = threadIdx.x >> 5;
    const int lane  = threadIdx.x & 31;

    // Query slice in registers (same for all warps): d = c*128 + lane*4 .. +3
    float4 q[8];
#pragma unroll
    for (int c = 0; c < 8; c++)
        q[c] = reinterpret_cast<const float4*>(query)[c * 32 + lane];

    float m = -3.0e38f;
    float s = 0.0f;
    float4 acc[8];
#pragma unroll
    for (int c = 0; c < 8; c++) acc[c] = make_float4(0.f, 0.f, 0.f, 0.f);

    const int row0 = split * (Lz / SPLITS) + warp * ROWS_PER_WARP;
    const int* mk = mask + (size_t)b * Lz;

    for (int i = 0; i < ROWS_PER_WARP; i++) {
        const int row = row0 + i;
        if (mk[row] == 0) continue;   // skip masked row: no 4KB load

        const float4* rp =
            reinterpret_cast<const float4*>(seq + ((size_t)b * Lz + row) * Dz);

        float4 r[8];
        float dot = 0.f;
#pragma unroll
        for (int c = 0; c < 8; c++) {
            r[c] = rp[c * 32 + lane];
            dot += r[c].x * q[c].x + r[c].y * q[c].y
                 + r[c].z * q[c].z + r[c].w * q[c].w;
        }
        // Warp all-reduce of the dot product
#pragma unroll
        for (int o = 16; o > 0; o >>= 1)
            dot += __shfl_xor_sync(0xffffffffu, dot, o);
        dot *= 0.03125f;          // 1/sqrt(1024)

        // Online softmax update
        const float mnew = fmaxf(m, dot);
        const float corr = __expf(m - mnew);
        const float w    = __expf(dot - mnew);
        s = s * corr + w;
#pragma unroll
        for (int c = 0; c < 8; c++) {
            acc[c].x = acc[c].x * corr + w * r[c].x;
            acc[c].y = acc[c].y * corr + w * r[c].y;
            acc[c].z = acc[c].z * corr + w * r[c].z;
            acc[c].w = acc[c].w * corr + w * r[c].w;
        }
        m = mnew;
    }

    // Write warp partial
    const int p = blockIdx.x * WARPS + warp;
    if (lane == 0) { g_m[p] = m; g_s[p] = s; }
    float4* ap = reinterpret_cast<float4*>(g_acc[p]);
#pragma unroll
    for (int c = 0; c < 8; c++) ap[c * 32 + lane] = acc[c];
}

// ---------------------------------------------------------------------------
// Pass 2: merge 128 partials per batch -> out[b, :]
// ---------------------------------------------------------------------------
__global__ void __launch_bounds__(256)
tap_pass2(float* __restrict__ out)
{
    const int b = blockIdx.x;
    const int t = threadIdx.x;

    __shared__ float ew[NPART];
    __shared__ float red[256];

    // Global max of partial maxima
    float mloc = -3.0e38f;
    if (t < NPART) mloc = g_m[b * NPART + t];
    red[t] = mloc;
    __syncthreads();
#pragma unroll
    for (int o = 128; o > 0; o >>= 1) {
        if (t < o) red[t] = fmaxf(red[t], red[t + o]);
        __syncthreads();
    }
    const float M = red[0];
    __syncthreads();

    // Total normalizer S = sum_i exp(m_i - M) * s_i ; cache e_i
    float sl = 0.f;
    if (t < NPART) {
        const float e = __expf(g_m[b * NPART + t] - M);
        ew[t] = e;
        sl = e * g_s[b * NPART + t];
    }
    red[t] = sl;
    __syncthreads();
#pragma unroll
    for (int o = 128; o > 0; o >>= 1) {
        if (t < o) red[t] += red[t + o];
        __syncthreads();
    }
    const float invS = 1.0f / red[0];
    __syncthreads();

    // out[b, d] = (sum_i e_i * acc_i[d]) / S ; thread t owns float4 #t
    float4 o4 = make_float4(0.f, 0.f, 0.f, 0.f);
    for (int i = 0; i < NPART; i++) {
        const float e = ew[i];
        if (e != 0.f) {
            const float4 a =
                reinterpret_cast<const float4*>(g_acc[b * NPART + i])[t];
            o4.x += e * a.x; o4.y += e * a.y;
            o4.z += e * a.z; o4.w += e * a.w;
        }
    }
    o4.x *= invS; o4.y *= invS; o4.z *= invS; o4.w *= invS;
    reinterpret_cast<float4*>(out)[b * (Dz / 4) + t] = o4;
}

// ---------------------------------------------------------------------------
extern "C" void kernel_launch(void* const* d_in, const int* in_sizes, int n_in,
                              void* d_out, int out_size)
{
    const float* seq   = (const float*)d_in[0];
    const int*   mask  = (const int*)d_in[1];
    const float* query = (const float*)d_in[2];
    float*       out   = (float*)d_out;

    tap_pass1<<<Bz * SPLITS, 256>>>(seq, mask, query);
    tap_pass2<<<Bz, 256>>>(out);
}

// round 3
// speedup vs baseline: 1.3536x; 1.3536x over previous
#include <cuda_runtime.h>
#include <math.h>

#define Bz 32
#define Lz 4096
#define Dz 1024
#define SPLITS 16
#define WARPS 8
#define ROWS_PER_WARP (Lz / SPLITS / WARPS)   // 32 (== warp size, used by ballot)
#define NPART SPLITS                          // 16 CTA-level partials per batch
#define TOTAL_PART (Bz * NPART)               // 512

// Scratch for CTA partials (no cudaMalloc allowed). 2 MB total.
__device__ float g_m[TOTAL_PART];
__device__ float g_s[TOTAL_PART];
__device__ float g_acc[TOTAL_PART][Dz];

// ---------------------------------------------------------------------------
// Pass 1: per-warp online softmax over 32 rows, then CTA-level merge of the
// 8 warp states through shared memory -> ONE partial per CTA.
// Lane owns 32 of the 1024 dims (8 x float4 at stride 128).
// Masked rows are skipped via a ballot bitmap (no per-row mask load stall,
// no 4KB row load for masked rows).
// ---------------------------------------------------------------------------
__global__ void __launch_bounds__(256, 2)
tap_pass1(const float* __restrict__ seq,
          const int* __restrict__ mask,       // bool marshalled as int32
          const float* __restrict__ query)
{
    const int b     = blockIdx.x / SPLITS;
    const int split = blockIdx.x % SPLITS;
    const int warp  = threadIdx.x >> 5;
    const int lane  = threadIdx.x & 31;

    __shared__ float sm_m[WARPS];
    __shared__ float sm_s[WARPS];
    __shared__ float sm_acc[WARPS][Dz];       // 32 KB

    // Query slice in registers: d = c*128 + lane*4 .. +3
    float4 q[8];
#pragma unroll
    for (int c = 0; c < 8; c++)
        q[c] = reinterpret_cast<const float4*>(query)[c * 32 + lane];

    float m = -3.0e38f;
    float s = 0.0f;
    float4 acc[8];
#pragma unroll
    for (int c = 0; c < 8; c++) acc[c] = make_float4(0.f, 0.f, 0.f, 0.f);

    const int row0 = split * (Lz / SPLITS) + warp * ROWS_PER_WARP;

    // One coalesced mask load per warp -> bitmap of unmasked rows.
    const int mv = mask[(size_t)b * Lz + row0 + lane];
    unsigned bits = __ballot_sync(0xffffffffu, mv != 0);

    while (bits) {
        const int i = __ffs(bits) - 1;
        bits &= bits - 1;
        const int row = row0 + i;

        const float4* rp =
            reinterpret_cast<const float4*>(seq + ((size_t)b * Lz + row) * Dz);

        float4 r[8];
        float dot = 0.f;
#pragma unroll
        for (int c = 0; c < 8; c++) {
            r[c] = rp[c * 32 + lane];
            dot += r[c].x * q[c].x + r[c].y * q[c].y
                 + r[c].z * q[c].z + r[c].w * q[c].w;
        }
#pragma unroll
        for (int o = 16; o > 0; o >>= 1)
            dot += __shfl_xor_sync(0xffffffffu, dot, o);
        dot *= 0.03125f;          // 1/sqrt(1024)

        const float mnew = fmaxf(m, dot);
        const float corr = __expf(m - mnew);
        const float w    = __expf(dot - mnew);
        s = s * corr + w;
#pragma unroll
        for (int c = 0; c < 8; c++) {
            acc[c].x = acc[c].x * corr + w * r[c].x;
            acc[c].y = acc[c].y * corr + w * r[c].y;
            acc[c].z = acc[c].z * corr + w * r[c].z;
            acc[c].w = acc[c].w * corr + w * r[c].w;
        }
        m = mnew;
    }

    // ---- CTA merge: 8 warp states -> 1 partial ----
    if (lane == 0) { sm_m[warp] = m; sm_s[warp] = s; }
    float4* wp = reinterpret_cast<float4*>(sm_acc[warp]);
#pragma unroll
    for (int c = 0; c < 8; c++) wp[c * 32 + lane] = acc[c];
    __syncthreads();

    // All threads redundantly compute M, e_w, S over the 8 warp states.
    float M = -3.0e38f;
#pragma unroll
    for (int w = 0; w < WARPS; w++) M = fmaxf(M, sm_m[w]);
    float e[WARPS];
    float S = 0.f;
#pragma unroll
    for (int w = 0; w < WARPS; w++) {
        e[w] = __expf(sm_m[w] - M);
        S += e[w] * sm_s[w];
    }

    // Thread t merges float4 #t of the 8 warp accumulators.
    const int t = threadIdx.x;                 // 0..255 covers Dz/4 float4s
    float4 o4 = make_float4(0.f, 0.f, 0.f, 0.f);
#pragma unroll
    for (int w = 0; w < WARPS; w++) {
        const float4 a = reinterpret_cast<const float4*>(sm_acc[w])[t];
        o4.x += e[w] * a.x; o4.y += e[w] * a.y;
        o4.z += e[w] * a.z; o4.w += e[w] * a.w;
    }

    const int p = blockIdx.x;                  // == b * SPLITS + split
    reinterpret_cast<float4*>(g_acc[p])[t] = o4;
    if (t == 0) { g_m[p] = M; g_s[p] = S; }
}

// ---------------------------------------------------------------------------
// Pass 2: merge 16 partials per batch -> out[b, :]   (2 MB total read)
// ---------------------------------------------------------------------------
__global__ void __launch_bounds__(256)
tap_pass2(float* __restrict__ out)
{
    const int b = blockIdx.x;
    const int t = threadIdx.x;

    __shared__ float sm_m[NPART];
    __shared__ float sm_s[NPART];

    if (t < NPART) {
        sm_m[t] = g_m[b * NPART + t];
        sm_s[t] = g_s[b * NPART + t];
    }
    __syncthreads();

    // Every thread computes M, e_i, invS over the 16 partials (cheap).
    float M = -3.0e38f;
#pragma unroll
    for (int i = 0; i < NPART; i++) M = fmaxf(M, sm_m[i]);
    float e[NPART];
    float S = 0.f;
#pragma unroll
    for (int i = 0; i < NPART; i++) {
        e[i] = __expf(sm_m[i] - M);
        S += e[i] * sm_s[i];
    }
    const float invS = 1.0f / S;

    // Thread t owns float4 #t of the output row; 16 independent loads (MLP=16).
    float4 o4 = make_float4(0.f, 0.f, 0.f, 0.f);
#pragma unroll
    for (int i = 0; i < NPART; i++) {
        const float4 a =
            reinterpret_cast<const float4*>(g_acc[b * NPART + i])[t];
        o4.x += e[i] * a.x; o4.y += e[i] * a.y;
        o4.z += e[i] * a.z; o4.w += e[i] * a.w;
    }
    o4.x *= invS; o4.y *= invS; o4.z *= invS; o4.w *= invS;
    reinterpret_cast<float4*>(out)[b * (Dz / 4) + t] = o4;
}

// ---------------------------------------------------------------------------
extern "C" void kernel_launch(void* const* d_in, const int* in_sizes, int n_in,
                              void* d_out, int out_size)
{
    const float* seq   = (const float*)d_in[0];
    const int*   mask  = (const int*)d_in[1];
    const float* query = (const float*)d_in[2];
    float*       out   = (float*)d_out;

    tap_pass1<<<Bz * SPLITS, 256>>>(seq, mask, query);
    tap_pass2<<<Bz, 256>>>(out);
}